// round 2
// baseline (speedup 1.0000x reference)
#include <cuda_runtime.h>

// TypeAttention reduces algebraically to alpha[e] = 1 / in_degree(dst[e]) per
// relation: every edge into a given dst carries the identical logit, so the
// per-dst edge softmax is uniform = 1/count. Output = concat over relations.
//
// Pipeline: memset counts -> histogram (int4, atomics) -> per-node reciprocal
// -> per-edge gather (int4 loads, float4 stores).

#define MAX_NODES 100000

__device__ int   g_cnt_ui[MAX_NODES];
__device__ int   g_cnt_iu[MAX_NODES];
__device__ float g_rcp_ui[MAX_NODES];
__device__ float g_rcp_iu[MAX_NODES];

__global__ void hist_kernel(const int* __restrict__ dst_ui,
                            const int* __restrict__ dst_iu, int E) {
    int i = blockIdx.x * blockDim.x + threadIdx.x;
    int base = i * 4;
    if (base + 3 < E) {
        int4 a = __ldg((const int4*)(dst_ui + base));
        atomicAdd(&g_cnt_ui[a.x], 1);
        atomicAdd(&g_cnt_ui[a.y], 1);
        atomicAdd(&g_cnt_ui[a.z], 1);
        atomicAdd(&g_cnt_ui[a.w], 1);
        int4 b = __ldg((const int4*)(dst_iu + base));
        atomicAdd(&g_cnt_iu[b.x], 1);
        atomicAdd(&g_cnt_iu[b.y], 1);
        atomicAdd(&g_cnt_iu[b.z], 1);
        atomicAdd(&g_cnt_iu[b.w], 1);
    } else {
        for (int j = base; j < E; j++) {
            atomicAdd(&g_cnt_ui[dst_ui[j]], 1);
            atomicAdd(&g_cnt_iu[dst_iu[j]], 1);
        }
    }
}

__global__ void recip_kernel(int n) {
    int i = blockIdx.x * blockDim.x + threadIdx.x;
    if (i < n) {
        int cu = g_cnt_ui[i];
        int ci = g_cnt_iu[i];
        // Precise fp32 division: bit-identical to reference's ex/denom.
        // Nodes with count 0 are never gathered; guard to avoid inf spam.
        g_rcp_ui[i] = 1.0f / (float)(cu > 0 ? cu : 1);
        g_rcp_iu[i] = 1.0f / (float)(ci > 0 ? ci : 1);
    }
}

__global__ void gather_kernel(const int* __restrict__ dst_ui,
                              const int* __restrict__ dst_iu,
                              float* __restrict__ out, int E) {
    int i = blockIdx.x * blockDim.x + threadIdx.x;
    int base = i * 4;
    if (base + 3 < E) {
        int4 a = __ldg((const int4*)(dst_ui + base));
        float4 ra;
        ra.x = g_rcp_ui[a.x];
        ra.y = g_rcp_ui[a.y];
        ra.z = g_rcp_ui[a.z];
        ra.w = g_rcp_ui[a.w];
        *(float4*)(out + base) = ra;

        int4 b = __ldg((const int4*)(dst_iu + base));
        float4 rb;
        rb.x = g_rcp_iu[b.x];
        rb.y = g_rcp_iu[b.y];
        rb.z = g_rcp_iu[b.z];
        rb.w = g_rcp_iu[b.w];
        *(float4*)(out + E + base) = rb;
    } else {
        for (int j = base; j < E; j++) {
            out[j]     = g_rcp_ui[dst_ui[j]];
            out[E + j] = g_rcp_iu[dst_iu[j]];
        }
    }
}

extern "C" void kernel_launch(void* const* d_in, const int* in_sizes, int n_in,
                              void* d_out, int out_size) {
    // Input order: h_user, h_item, Wl_user, bl_user, Wl_item, bl_item,
    //              Wr_user, br_user, Wr_item, br_item, attn_w,
    //              src_ui, dst_ui, src_iu, dst_iu
    const int* dst_ui = (const int*)d_in[12];
    const int* dst_iu = (const int*)d_in[14];
    float* out = (float*)d_out;

    int D  = in_sizes[3];            // bl_user has D elements
    int Nn = in_sizes[0] / D;        // h_user is (N, D)
    if (Nn > MAX_NODES) Nn = MAX_NODES;
    int E = in_sizes[12];            // dst_ui has E elements

    void* p_cnt_ui = nullptr;
    void* p_cnt_iu = nullptr;
    cudaGetSymbolAddress(&p_cnt_ui, g_cnt_ui);
    cudaGetSymbolAddress(&p_cnt_iu, g_cnt_iu);
    cudaMemsetAsync(p_cnt_ui, 0, (size_t)Nn * sizeof(int));
    cudaMemsetAsync(p_cnt_iu, 0, (size_t)Nn * sizeof(int));

    const int TPB = 256;
    int e4 = (E + 3) / 4;
    hist_kernel<<<(e4 + TPB - 1) / TPB, TPB>>>(dst_ui, dst_iu, E);
    recip_kernel<<<(Nn + TPB - 1) / TPB, TPB>>>(Nn);
    gather_kernel<<<(e4 + TPB - 1) / TPB, TPB>>>(dst_ui, dst_iu, out, E);
}